// round 4
// baseline (speedup 1.0000x reference)
#include <cuda_runtime.h>
#include <cuda_bf16.h>
#include <cstdint>

// out[v, g, v2, d] = W[GE[v,g] % 3, d] + b[d]
//   GE: [512, 4, 1] int32, W: [3, 64] f32, b: [64] f32
//   out: [512, 4, 512, 64] f32  (256 MB) — constant along v2.
//
// One block per (v,g) pair. Build the 256-B row once, replicate it 64x in
// SMEM (16 KB), then stream 128 KB to GMEM via 8 x cp.async.bulk (TMA),
// removing the SM store path from the hot loop.

static constexpr int V = 512;
static constexpr int G = 4;
static constexpr int D = 64;
static constexpr int D4 = D / 4;              // 16 float4 per row
static constexpr int THREADS = 256;
static constexpr int REP = 64;                // row copies in SMEM
static constexpr int SMEM_BYTES = REP * D * 4;       // 16 KB
static constexpr int BULKS = (V / REP);              // 8 bulk copies of 16 KB

__device__ __forceinline__ uint32_t smem_u32(const void* p)
{
    uint32_t a;
    asm("{ .reg .u64 t; cvta.to.shared.u64 t, %1; cvt.u32.u64 %0, t; }"
        : "=r"(a) : "l"(p));
    return a;
}

__global__ void __launch_bounds__(THREADS, 8)
gembed_tma_kernel(const int* __restrict__ GE,
                  const float* __restrict__ W,
                  const float* __restrict__ b,
                  float* __restrict__ out)
{
    __shared__ alignas(128) float4 srow[REP * D4];   // 16 KB

    const int pair = blockIdx.x;              // v*G + g
    const int t    = threadIdx.x;
    const int d4   = t & (D4 - 1);

    const int idx = GE[pair] % 3;

    const float4 w  = reinterpret_cast<const float4*>(W + idx * D)[d4];
    const float4 bb = reinterpret_cast<const float4*>(b)[d4];
    float4 val;
    val.x = w.x + bb.x;
    val.y = w.y + bb.y;
    val.z = w.z + bb.z;
    val.w = w.w + bb.w;

    // Fill the 64-copy SMEM replica: 256 threads x float4 = 4 KB per pass.
    const int c0 = t >> 4;                    // 0..15
    #pragma unroll
    for (int c = c0; c < REP; c += THREADS / D4) {
        srow[c * D4 + d4] = val;
    }
    __syncthreads();
    // Order generic-proxy SMEM writes before async-proxy (TMA) reads.
    asm volatile("fence.proxy.async.shared::cta;" ::: "memory");

    if (t == 0) {
        const uint32_t s = smem_u32(srow);
        char* g = reinterpret_cast<char*>(out) + (size_t)pair * (size_t)(V * D * 4);
        #pragma unroll
        for (int k = 0; k < BULKS; k++) {
            asm volatile(
                "cp.async.bulk.global.shared::cta.bulk_group [%0], [%1], %2;"
                :: "l"(g + (size_t)k * SMEM_BYTES), "r"(s), "n"(SMEM_BYTES)
                : "memory");
        }
        asm volatile("cp.async.bulk.commit_group;" ::: "memory");
        asm volatile("cp.async.bulk.wait_group.read 0;" ::: "memory");
    }
}

extern "C" void kernel_launch(void* const* d_in, const int* in_sizes, int n_in,
                              void* d_out, int out_size)
{
    const int*   GE = (const int*)d_in[0];
    const float* W  = (const float*)d_in[1];
    const float* b  = (const float*)d_in[2];
    float* out = (float*)d_out;

    (void)in_sizes; (void)n_in; (void)out_size;

    gembed_tma_kernel<<<V * G, THREADS>>>(GE, W, b, out);
}